// round 13
// baseline (speedup 1.0000x reference)
#include <cuda_runtime.h>
#include <cstdint>

#define BB 8
#define NN 8192
#define CIN 64
#define COUT 128
#define MM 2048
#define KNB 16
#define EPSF 1e-5f

// 32 MB scratch for h = relu(BN(x @ W^T))  (B*N*COUT floats)
__device__ float g_h[(size_t)BB * NN * COUT];

typedef unsigned long long ull;

__device__ __forceinline__ unsigned redux_max_u32(unsigned v) {
    unsigned r;
    asm("redux.sync.max.u32 %0, %1, 0xffffffff;" : "=r"(r) : "r"(v));
    return r;
}

// ---- packed f32x2 helpers (Blackwell; PTX-only, ptxas never auto-fuses) ----
__device__ __forceinline__ ull pk2(float lo, float hi) {
    ull r; asm("mov.b64 %0, {%1, %2};" : "=l"(r) : "f"(lo), "f"(hi)); return r;
}
__device__ __forceinline__ void upk2(ull v, float& lo, float& hi) {
    asm("mov.b64 {%0, %1}, %2;" : "=f"(lo), "=f"(hi) : "l"(v));
}
__device__ __forceinline__ ull addx2(ull a, ull b) {
    ull r; asm("add.rn.f32x2 %0, %1, %2;" : "=l"(r) : "l"(a), "l"(b)); return r;
}
__device__ __forceinline__ ull mulx2(ull a, ull b) {
    ull r; asm("mul.rn.f32x2 %0, %1, %2;" : "=l"(r) : "l"(a), "l"(b)); return r;
}
__device__ __forceinline__ ull fmafx2(ull a, ull b, ull c) {
    ull r; asm("fma.rn.f32x2 %0, %1, %2, %3;" : "=l"(r) : "l"(a), "l"(b), "l"(c)); return r;
}

// Reference-exact squared norm: ((x*x + y*y) + z*z), no fma contraction. (KNN)
__device__ __forceinline__ float sq3(float a0, float a1, float a2) {
    return __fadd_rn(__fadd_rn(__fmul_rn(a0, a0), __fmul_rn(a1, a1)),
                     __fmul_rn(a2, a2));
}

// Dynamic smem sizing:
//  FPS role : 3*8192 floats (p cache) + 4 x u64 key slots  = 98304 + 32 B
//  MLP role : 2*64*132 floats (xs, ws) + 3*128 floats (bn) = 69120 B
#define SMEM1 98560

extern __shared__ float smem_dyn[];

// ---------------------------------------------------------------------------
// Kernel 1: blocks 0..7  -> FPS (one cloud each, writes p_out region of out)
//           blocks 8..519 -> pointwise MLP + BN + ReLU into g_h
// ---------------------------------------------------------------------------
__global__ __launch_bounds__(1024)
void k1_fps_mlp(const float* __restrict__ x,
                const float* __restrict__ p,
                const float* __restrict__ W,
                const float* __restrict__ gamma,
                const float* __restrict__ beta,
                const float* __restrict__ rmean,
                const float* __restrict__ rvar,
                float* __restrict__ out)
{
    if (blockIdx.x < BB) {
        // ======================= FPS =======================
        const int b   = blockIdx.x;
        const int tid = threadIdx.x;

        float* spx = smem_dyn;
        float* spy = smem_dyn + NN;
        float* spz = smem_dyn + 2 * NN;
        ull*   skey = (ull*)(smem_dyn + 3 * NN);   // 4 rotating argmax slots

        const float* pb = p + (size_t)b * NN * 3;

        // thread owns points i = tid + k*1024, k=0..7; packed in pairs (2j, 2j+1)
        float pxs[8], pys[8], pzs[8];
        float dd[8];
        #pragma unroll
        for (int k = 0; k < 8; k++) {
            int i = tid + k * 1024;
            float a0 = pb[i * 3 + 0];
            float a1 = pb[i * 3 + 1];
            float a2 = pb[i * 3 + 2];
            pxs[k] = a0; pys[k] = a1; pzs[k] = a2;
            spx[i] = a0; spy[i] = a1; spz[i] = a2;
            dd[k] = __int_as_float(0x7f800000);  // +inf
        }
        ull px2[4], py2[4], pz2[4];
        #pragma unroll
        for (int j = 0; j < 4; j++) {
            px2[j] = pk2(pxs[2 * j], pxs[2 * j + 1]);
            py2[j] = pk2(pys[2 * j], pys[2 * j + 1]);
            pz2[j] = pk2(pzs[2 * j], pzs[2 * j + 1]);
        }

        float* pout = out + (size_t)BB * MM * COUT + (size_t)b * MM * 3;
        if (tid == 0) {  // index 0 is always the first sample
            pout[0] = pb[0]; pout[1] = pb[1]; pout[2] = pb[2];
            skey[0] = 0; skey[1] = 0; skey[2] = 0; skey[3] = 0;
        }
        __syncthreads();

        int last = 0;
        for (int m = 1; m < MM; m++) {
            const float lx = spx[last], ly = spy[last], lz = spz[last];
            const ull nlx2 = pk2(-lx, -lx);
            const ull nly2 = pk2(-ly, -ly);
            const ull nlz2 = pk2(-lz, -lz);

            #pragma unroll
            for (int j = 0; j < 4; j++) {
                ull dx = addx2(px2[j], nlx2);
                ull dy = addx2(py2[j], nly2);
                ull dz = addx2(pz2[j], nlz2);
                ull t  = fmafx2(dz, dz, fmafx2(dy, dy, mulx2(dx, dx)));
                float t0, t1; upk2(t, t0, t1);
                dd[2 * j]     = fminf(dd[2 * j],     t0);
                dd[2 * j + 1] = fminf(dd[2 * j + 1], t1);
            }
            // max tree over the 8 residual distances
            float m0 = fmaxf(dd[0], dd[1]);
            float m1 = fmaxf(dd[2], dd[3]);
            float m2 = fmaxf(dd[4], dd[5]);
            float m3 = fmaxf(dd[6], dd[7]);
            float bm = fmaxf(fmaxf(m0, m1), fmaxf(m2, m3));

            // dists >= 0 -> float bits order-preserving as u32
            unsigned bmb = __float_as_uint(bm);
            unsigned wm  = redux_max_u32(bmb);
            if (bmb == wm) {
                // this thread's lowest global index attaining its max
                int loc = 0;
                #pragma unroll
                for (int k = 7; k >= 0; k--)
                    if (__float_as_uint(dd[k]) == bmb) loc = k * 1024 + tid;
                // value-major key; ~idx makes ties pick the LOWEST index
                ull key = ((ull)bmb << 32) | (unsigned)(~loc);
                atomicMax(&skey[m & 3], key);
            }
            if (tid == 0) skey[(m + 1) & 3] = 0;   // reset slot for iter m+1 (R=4 safe)
            __syncthreads();
            last = (int)(unsigned)(~(unsigned)skey[m & 3]);
            if (tid == 0) {
                pout[m * 3 + 0] = spx[last];
                pout[m * 3 + 1] = spy[last];
                pout[m * 3 + 2] = spz[last];
            }
        }
    } else {
        // ======================= MLP =======================
        const int mb      = blockIdx.x - BB;
        const int rowBase = mb * 128;          // 512 blocks * 128 rows = 65536
        const int tid     = threadIdx.x;

        float* xs    = smem_dyn;                 // [64][132] : xs[c*132 + row]
        float* ws    = smem_dyn + 64 * 132;      // [64][132] : ws[c*132 + o]
        float* smean = smem_dyn + 2 * 64 * 132;  // [128]
        float* srsg  = smean + 128;              // rs*gamma
        float* sbeta = srsg + 128;

        #pragma unroll
        for (int k = 0; k < 8; k++) {
            int e = tid + k * 1024;              // 8192 elements each
            int r = e >> 6, c = e & 63;
            xs[c * 132 + r] = x[(size_t)(rowBase + r) * CIN + c];
            ws[c * 132 + r] = W[(size_t)r * CIN + c];   // r plays the role of o
        }
        if (tid < 128) {
            float rs = rsqrtf(rvar[tid] + EPSF);
            smean[tid] = rmean[tid];
            srsg[tid]  = rs * gamma[tid];
            sbeta[tid] = beta[tid];
        }
        __syncthreads();

        const int ty = tid >> 5, tx = tid & 31;   // 32x32 thread grid
        float acc[4][4];
        #pragma unroll
        for (int i = 0; i < 4; i++)
            #pragma unroll
            for (int j = 0; j < 4; j++) acc[i][j] = 0.0f;

        #pragma unroll 8
        for (int c = 0; c < 64; c++) {
            float4 xv = *(const float4*)&xs[c * 132 + ty * 4];
            float4 wv = *(const float4*)&ws[c * 132 + tx * 4];
            float xr[4] = {xv.x, xv.y, xv.z, xv.w};
            float wr[4] = {wv.x, wv.y, wv.z, wv.w};
            #pragma unroll
            for (int i = 0; i < 4; i++)
                #pragma unroll
                for (int j = 0; j < 4; j++)
                    acc[i][j] = __fmaf_rn(xr[i], wr[j], acc[i][j]);
        }

        float* hb = g_h + (size_t)rowBase * COUT;
        #pragma unroll
        for (int i = 0; i < 4; i++) {
            int r = ty * 4 + i;
            float4 o;
            float m0 = smean[tx * 4 + 0], g0 = srsg[tx * 4 + 0], b0 = sbeta[tx * 4 + 0];
            float m1 = smean[tx * 4 + 1], g1 = srsg[tx * 4 + 1], b1 = sbeta[tx * 4 + 1];
            float m2 = smean[tx * 4 + 2], g2 = srsg[tx * 4 + 2], b2 = sbeta[tx * 4 + 2];
            float m3 = smean[tx * 4 + 3], g3 = srsg[tx * 4 + 3], b3 = sbeta[tx * 4 + 3];
            o.x = fmaxf(0.0f, (acc[i][0] - m0) * g0 + b0);
            o.y = fmaxf(0.0f, (acc[i][1] - m1) * g1 + b1);
            o.z = fmaxf(0.0f, (acc[i][2] - m2) * g2 + b2);
            o.w = fmaxf(0.0f, (acc[i][3] - m3) * g3 + b3);
            *(float4*)&hb[(size_t)r * COUT + tx * 4] = o;
        }
    }
}

// ---------------------------------------------------------------------------
// Kernel 2: KNN (top-16 by squared distance, set semantics) + gather + maxpool
//   grid: 8 batches * 16 blocks, 128 threads (1 query / thread)
//   d2 replicates reference:  d2 = (|q|^2 + |p|^2) - 2*(q.p)
//     |.|^2 : ((x*x + y*y) + z*z)  non-fma
//     q.p   : fma(qz,pz, fma(qy,py, qx*px))  k-ascending (gemm convention)
// ---------------------------------------------------------------------------
__global__ __launch_bounds__(128)
void k2_knn_pool(const float* __restrict__ p, float* __restrict__ out)
{
    __shared__ float4 sp4[2048];          // candidate tile (x,y,z,|p|^2)
    __shared__ int    snbr[128][KNB];

    const int blk = blockIdx.x;
    const int b   = blk >> 4;
    const int qb  = (blk & 15) * 128;
    const int tid = threadIdx.x;

    const float* pb   = p + (size_t)b * NN * 3;
    const float* pout = out + (size_t)BB * MM * COUT + (size_t)b * MM * 3;

    const int   m  = qb + tid;
    const float qx = pout[m * 3 + 0];
    const float qy = pout[m * 3 + 1];
    const float qz = pout[m * 3 + 2];
    const float sqo = sq3(qx, qy, qz);      // |q|^2, reference rounding

    float bd[KNB];
    int   bi[KNB];
    #pragma unroll
    for (int j = 0; j < KNB; j++) { bd[j] = __int_as_float(0x7f800000); bi[j] = 0x7fffffff; }
    float wv = __int_as_float(0x7f800000);   // current worst value in set
    int   wi = 0x7fffffff;                   // its point index
    int   wslot = 0;

    for (int t0 = 0; t0 < NN; t0 += 2048) {
        __syncthreads();
        #pragma unroll
        for (int k = 0; k < 16; k++) {
            int i  = tid + k * 128;
            int gi = t0 + i;
            float a0 = pb[gi * 3 + 0];
            float a1 = pb[gi * 3 + 1];
            float a2 = pb[gi * 3 + 2];
            sp4[i] = make_float4(a0, a1, a2, sq3(a0, a1, a2));
        }
        __syncthreads();

        #pragma unroll 4
        for (int t = 0; t < 2048; t++) {
            float4 c = sp4[t];
            // q.p with k-ascending fma accumulation (acc starts at qx*px)
            float dot = __fmaf_rn(qz, c.z, __fmaf_rn(qy, c.y, __fmul_rn(qx, c.x)));
            // d2 = (sqo + sqp) - 2*dot, matching (A + B) - C association
            float key = __fsub_rn(__fadd_rn(sqo, c.w), __fmul_rn(2.0f, dot));
            if (key < wv) {                            // strict: ties keep earlier idx
                int idx = t0 + t;
                #pragma unroll
                for (int j = 0; j < KNB; j++)
                    if (j == wslot) { bd[j] = key; bi[j] = idx; }
                // recompute worst; on value ties evict the larger point index
                wv = __int_as_float(0xff800000); wi = -1; wslot = 0;
                #pragma unroll
                for (int j = 0; j < KNB; j++) {
                    bool g = (bd[j] > wv) || (bd[j] == wv && bi[j] > wi);
                    if (g) { wv = bd[j]; wi = bi[j]; wslot = j; }
                }
            }
        }
    }

    #pragma unroll
    for (int j = 0; j < KNB; j++) snbr[tid][j] = bi[j];
    __syncthreads();

    // ---- gather + maxpool: warp per query, lanes = 4 channels each ----
    const int wid = tid >> 5, lane = tid & 31;
    const float* hb = g_h + (size_t)b * NN * COUT;
    for (int it = 0; it < 32; it++) {
        int qi = wid * 32 + it;
        float4 acc = make_float4(__int_as_float(0xff800000), __int_as_float(0xff800000),
                                 __int_as_float(0xff800000), __int_as_float(0xff800000));
        #pragma unroll
        for (int k = 0; k < KNB; k++) {
            int nb = snbr[qi][k];
            float4 v = *(const float4*)&hb[(size_t)nb * COUT + lane * 4];
            acc.x = fmaxf(acc.x, v.x);
            acc.y = fmaxf(acc.y, v.y);
            acc.z = fmaxf(acc.z, v.z);
            acc.w = fmaxf(acc.w, v.w);
        }
        *(float4*)&out[((size_t)b * MM + qb + qi) * COUT + lane * 4] = acc;
    }
}

// ---------------------------------------------------------------------------
extern "C" void kernel_launch(void* const* d_in, const int* in_sizes, int n_in,
                              void* d_out, int out_size)
{
    const float* x     = (const float*)d_in[0];
    const float* p     = (const float*)d_in[1];
    const float* W     = (const float*)d_in[2];
    const float* gamma = (const float*)d_in[3];
    const float* beta  = (const float*)d_in[4];
    const float* rm    = (const float*)d_in[5];
    const float* rv    = (const float*)d_in[6];
    float* out = (float*)d_out;

    cudaFuncSetAttribute(k1_fps_mlp, cudaFuncAttributeMaxDynamicSharedMemorySize, SMEM1);

    // blocks 0..7: FPS (serial bottleneck, 8 SMs); blocks 8..519: MLP (rest of chip)
    k1_fps_mlp<<<BB + 512, 1024, SMEM1>>>(x, p, W, gamma, beta, rm, rv, out);
    // KNN needs p_out (from FPS) and g_h (from MLP)
    k2_knn_pool<<<128, 128>>>(p, out);
}

// round 14
// speedup vs baseline: 1.0339x; 1.0339x over previous
#include <cuda_runtime.h>
#include <cstdint>

#define BB 8
#define NN 8192
#define CIN 64
#define COUT 128
#define MM 2048
#define KNB 16
#define EPSF 1e-5f

#define FPS_T 512          // FPS worker threads per block
#define PPT   (NN / FPS_T) // 16 points per thread

// 32 MB scratch for h = relu(BN(x @ W^T))  (B*N*COUT floats)
__device__ float g_h[(size_t)BB * NN * COUT];

typedef unsigned long long ull;

__device__ __forceinline__ unsigned redux_max_u32(unsigned v) {
    unsigned r;
    asm("redux.sync.max.u32 %0, %1, 0xffffffff;" : "=r"(r) : "r"(v));
    return r;
}
__device__ __forceinline__ void bar_fps() {   // named barrier, 512 threads
    asm volatile("bar.sync 1, %0;" :: "n"(FPS_T) : "memory");
}

// ---- packed f32x2 helpers (Blackwell; PTX-only, ptxas never auto-fuses) ----
__device__ __forceinline__ ull pk2(float lo, float hi) {
    ull r; asm("mov.b64 %0, {%1, %2};" : "=l"(r) : "f"(lo), "f"(hi)); return r;
}
__device__ __forceinline__ void upk2(ull v, float& lo, float& hi) {
    asm("mov.b64 {%0, %1}, %2;" : "=f"(lo), "=f"(hi) : "l"(v));
}
__device__ __forceinline__ ull addx2(ull a, ull b) {
    ull r; asm("add.rn.f32x2 %0, %1, %2;" : "=l"(r) : "l"(a), "l"(b)); return r;
}
__device__ __forceinline__ ull mulx2(ull a, ull b) {
    ull r; asm("mul.rn.f32x2 %0, %1, %2;" : "=l"(r) : "l"(a), "l"(b)); return r;
}
__device__ __forceinline__ ull fmafx2(ull a, ull b, ull c) {
    ull r; asm("fma.rn.f32x2 %0, %1, %2, %3;" : "=l"(r) : "l"(a), "l"(b), "l"(c)); return r;
}

// Reference-exact squared norm: ((x*x + y*y) + z*z), no fma contraction. (KNN)
__device__ __forceinline__ float sq3(float a0, float a1, float a2) {
    return __fadd_rn(__fadd_rn(__fmul_rn(a0, a0), __fmul_rn(a1, a1)),
                     __fmul_rn(a2, a2));
}

// Dynamic smem sizing:
//  FPS role : 3*8192 floats (p cache) + warpmax[16] + sgidx[2]
//  MLP role : 2*64*132 floats (xs, ws) + 3*128 floats (bn) = 69120 B
#define SMEM1 98560

extern __shared__ float smem_dyn[];

// ---------------------------------------------------------------------------
// Kernel 1: blocks 0..7  -> FPS (one cloud each, writes p_out region of out)
//           blocks 8..519 -> pointwise MLP + BN + ReLU into g_h
// ---------------------------------------------------------------------------
__global__ __launch_bounds__(1024)
void k1_fps_mlp(const float* __restrict__ x,
                const float* __restrict__ p,
                const float* __restrict__ W,
                const float* __restrict__ gamma,
                const float* __restrict__ beta,
                const float* __restrict__ rmean,
                const float* __restrict__ rvar,
                float* __restrict__ out)
{
    if (blockIdx.x < BB) {
        // ======================= FPS (512 worker threads) =======================
        const int tid = threadIdx.x;
        if (tid >= FPS_T) return;               // named barrier counts 512 only
        const int b    = blockIdx.x;
        const int wid  = tid >> 5, lane = tid & 31;

        float* spx = smem_dyn;
        float* spy = smem_dyn + NN;
        float* spz = smem_dyn + 2 * NN;
        unsigned* warpmax = (unsigned*)(smem_dyn + 3 * NN);   // [16]
        int*      sgidx   = (int*)(warpmax + 16);             // [2] rotating

        const float* pb = p + (size_t)b * NN * 3;

        // thread owns points i = tid + k*512, k=0..15; packed in pairs
        float pxs[PPT], pys[PPT], pzs[PPT], dd[PPT];
        #pragma unroll
        for (int k = 0; k < PPT; k++) {
            int i = tid + k * FPS_T;
            float a0 = pb[i * 3 + 0];
            float a1 = pb[i * 3 + 1];
            float a2 = pb[i * 3 + 2];
            pxs[k] = a0; pys[k] = a1; pzs[k] = a2;
            spx[i] = a0; spy[i] = a1; spz[i] = a2;
            dd[k] = __int_as_float(0x7f800000);  // +inf
        }
        ull px2[PPT / 2], py2[PPT / 2], pz2[PPT / 2];
        #pragma unroll
        for (int j = 0; j < PPT / 2; j++) {
            px2[j] = pk2(pxs[2 * j], pxs[2 * j + 1]);
            py2[j] = pk2(pys[2 * j], pys[2 * j + 1]);
            pz2[j] = pk2(pzs[2 * j], pzs[2 * j + 1]);
        }

        float* pout = out + (size_t)BB * MM * COUT + (size_t)b * MM * 3;
        if (tid == 0) {  // index 0 is always the first sample
            pout[0] = pb[0]; pout[1] = pb[1]; pout[2] = pb[2];
            sgidx[0] = 0x7fffffff; sgidx[1] = 0x7fffffff;
        }
        bar_fps();

        int last = 0;
        for (int m = 1; m < MM; m++) {
            const float lx = spx[last], ly = spy[last], lz = spz[last];
            const ull nlx2 = pk2(-lx, -lx);
            const ull nly2 = pk2(-ly, -ly);
            const ull nlz2 = pk2(-lz, -lz);

            #pragma unroll
            for (int j = 0; j < PPT / 2; j++) {
                ull dx = addx2(px2[j], nlx2);
                ull dy = addx2(py2[j], nly2);
                ull dz = addx2(pz2[j], nlz2);
                ull t  = fmafx2(dz, dz, fmafx2(dy, dy, mulx2(dx, dx)));
                float t0, t1; upk2(t, t0, t1);
                dd[2 * j]     = fminf(dd[2 * j],     t0);
                dd[2 * j + 1] = fminf(dd[2 * j + 1], t1);
            }
            // max tree over the 16 residual distances
            float mx01 = fmaxf(fmaxf(dd[0], dd[1]),   fmaxf(dd[2], dd[3]));
            float mx23 = fmaxf(fmaxf(dd[4], dd[5]),   fmaxf(dd[6], dd[7]));
            float mx45 = fmaxf(fmaxf(dd[8], dd[9]),   fmaxf(dd[10], dd[11]));
            float mx67 = fmaxf(fmaxf(dd[12], dd[13]), fmaxf(dd[14], dd[15]));
            float bm = fmaxf(fmaxf(mx01, mx23), fmaxf(mx45, mx67));

            // dists >= 0 -> float bits order-preserving as u32
            unsigned bmb = __float_as_uint(bm);
            unsigned wm  = redux_max_u32(bmb);
            if (lane == 0) warpmax[wid] = wm;
            if (tid == 0) sgidx[(m + 1) & 1] = 0x7fffffff;  // reset next slot
            bar_fps();

            // every warp computes the block max itself (no 2nd reduction barrier)
            unsigned bv = redux_max_u32(warpmax[lane & 15]);
            if (bmb == bv) {
                // this thread's lowest global index attaining the block max
                int loc = 0x7fffffff;
                #pragma unroll
                for (int k = PPT - 1; k >= 0; k--)
                    if (__float_as_uint(dd[k]) == bv) loc = k * FPS_T + tid;
                atomicMin(&sgidx[m & 1], loc);   // ~1-2 threads total: cheap
            }
            bar_fps();

            last = sgidx[m & 1];
            if (tid == 0) {
                pout[m * 3 + 0] = spx[last];
                pout[m * 3 + 1] = spy[last];
                pout[m * 3 + 2] = spz[last];
            }
        }
    } else {
        // ======================= MLP =======================
        const int mb      = blockIdx.x - BB;
        const int rowBase = mb * 128;          // 512 blocks * 128 rows = 65536
        const int tid     = threadIdx.x;

        float* xs    = smem_dyn;                 // [64][132] : xs[c*132 + row]
        float* ws    = smem_dyn + 64 * 132;      // [64][132] : ws[c*132 + o]
        float* smean = smem_dyn + 2 * 64 * 132;  // [128]
        float* srsg  = smean + 128;              // rs*gamma
        float* sbeta = srsg + 128;

        #pragma unroll
        for (int k = 0; k < 8; k++) {
            int e = tid + k * 1024;              // 8192 elements each
            int r = e >> 6, c = e & 63;
            xs[c * 132 + r] = x[(size_t)(rowBase + r) * CIN + c];
            ws[c * 132 + r] = W[(size_t)r * CIN + c];   // r plays the role of o
        }
        if (tid < 128) {
            float rs = rsqrtf(rvar[tid] + EPSF);
            smean[tid] = rmean[tid];
            srsg[tid]  = rs * gamma[tid];
            sbeta[tid] = beta[tid];
        }
        __syncthreads();

        const int ty = tid >> 5, tx = tid & 31;   // 32x32 thread grid
        float acc[4][4];
        #pragma unroll
        for (int i = 0; i < 4; i++)
            #pragma unroll
            for (int j = 0; j < 4; j++) acc[i][j] = 0.0f;

        #pragma unroll 8
        for (int c = 0; c < 64; c++) {
            float4 xv = *(const float4*)&xs[c * 132 + ty * 4];
            float4 wv = *(const float4*)&ws[c * 132 + tx * 4];
            float xr[4] = {xv.x, xv.y, xv.z, xv.w};
            float wr[4] = {wv.x, wv.y, wv.z, wv.w};
            #pragma unroll
            for (int i = 0; i < 4; i++)
                #pragma unroll
                for (int j = 0; j < 4; j++)
                    acc[i][j] = __fmaf_rn(xr[i], wr[j], acc[i][j]);
        }

        float* hb = g_h + (size_t)rowBase * COUT;
        #pragma unroll
        for (int i = 0; i < 4; i++) {
            int r = ty * 4 + i;
            float4 o;
            float m0 = smean[tx * 4 + 0], g0 = srsg[tx * 4 + 0], b0 = sbeta[tx * 4 + 0];
            float m1 = smean[tx * 4 + 1], g1 = srsg[tx * 4 + 1], b1 = sbeta[tx * 4 + 1];
            float m2 = smean[tx * 4 + 2], g2 = srsg[tx * 4 + 2], b2 = sbeta[tx * 4 + 2];
            float m3 = smean[tx * 4 + 3], g3 = srsg[tx * 4 + 3], b3 = sbeta[tx * 4 + 3];
            o.x = fmaxf(0.0f, (acc[i][0] - m0) * g0 + b0);
            o.y = fmaxf(0.0f, (acc[i][1] - m1) * g1 + b1);
            o.z = fmaxf(0.0f, (acc[i][2] - m2) * g2 + b2);
            o.w = fmaxf(0.0f, (acc[i][3] - m3) * g3 + b3);
            *(float4*)&hb[(size_t)r * COUT + tx * 4] = o;
        }
    }
}

// ---------------------------------------------------------------------------
// Kernel 2: KNN (top-16 by squared distance, set semantics) + gather + maxpool
//   grid: 8 batches * 16 blocks, 128 threads (1 query / thread)
//   d2 replicates reference:  d2 = (|q|^2 + |p|^2) - 2*(q.p)
// ---------------------------------------------------------------------------
__global__ __launch_bounds__(128)
void k2_knn_pool(const float* __restrict__ p, float* __restrict__ out)
{
    __shared__ float4 sp4[2048];          // candidate tile (x,y,z,|p|^2)
    __shared__ int    snbr[128][KNB];

    const int blk = blockIdx.x;
    const int b   = blk >> 4;
    const int qb  = (blk & 15) * 128;
    const int tid = threadIdx.x;

    const float* pb   = p + (size_t)b * NN * 3;
    const float* pout = out + (size_t)BB * MM * COUT + (size_t)b * MM * 3;

    const int   m  = qb + tid;
    const float qx = pout[m * 3 + 0];
    const float qy = pout[m * 3 + 1];
    const float qz = pout[m * 3 + 2];
    const float sqo = sq3(qx, qy, qz);      // |q|^2, reference rounding

    float bd[KNB];
    int   bi[KNB];
    #pragma unroll
    for (int j = 0; j < KNB; j++) { bd[j] = __int_as_float(0x7f800000); bi[j] = 0x7fffffff; }
    float wv = __int_as_float(0x7f800000);   // current worst value in set
    int   wi = 0x7fffffff;                   // its point index
    int   wslot = 0;

    for (int t0 = 0; t0 < NN; t0 += 2048) {
        __syncthreads();
        #pragma unroll
        for (int k = 0; k < 16; k++) {
            int i  = tid + k * 128;
            int gi = t0 + i;
            float a0 = pb[gi * 3 + 0];
            float a1 = pb[gi * 3 + 1];
            float a2 = pb[gi * 3 + 2];
            sp4[i] = make_float4(a0, a1, a2, sq3(a0, a1, a2));
        }
        __syncthreads();

        #pragma unroll 4
        for (int t = 0; t < 2048; t++) {
            float4 c = sp4[t];
            // q.p with k-ascending fma accumulation (acc starts at qx*px)
            float dot = __fmaf_rn(qz, c.z, __fmaf_rn(qy, c.y, __fmul_rn(qx, c.x)));
            // d2 = (sqo + sqp) - 2*dot, matching (A + B) - C association
            float key = __fsub_rn(__fadd_rn(sqo, c.w), __fmul_rn(2.0f, dot));
            if (key < wv) {                            // strict: ties keep earlier idx
                int idx = t0 + t;
                #pragma unroll
                for (int j = 0; j < KNB; j++)
                    if (j == wslot) { bd[j] = key; bi[j] = idx; }
                // recompute worst; on value ties evict the larger point index
                wv = __int_as_float(0xff800000); wi = -1; wslot = 0;
                #pragma unroll
                for (int j = 0; j < KNB; j++) {
                    bool g = (bd[j] > wv) || (bd[j] == wv && bi[j] > wi);
                    if (g) { wv = bd[j]; wi = bi[j]; wslot = j; }
                }
            }
        }
    }

    #pragma unroll
    for (int j = 0; j < KNB; j++) snbr[tid][j] = bi[j];
    __syncthreads();

    // ---- gather + maxpool: warp per query, lanes = 4 channels each ----
    const int wid = tid >> 5, lane = tid & 31;
    const float* hb = g_h + (size_t)b * NN * COUT;
    for (int it = 0; it < 32; it++) {
        int qi = wid * 32 + it;
        float4 acc = make_float4(__int_as_float(0xff800000), __int_as_float(0xff800000),
                                 __int_as_float(0xff800000), __int_as_float(0xff800000));
        #pragma unroll
        for (int k = 0; k < KNB; k++) {
            int nb = snbr[qi][k];
            float4 v = *(const float4*)&hb[(size_t)nb * COUT + lane * 4];
            acc.x = fmaxf(acc.x, v.x);
            acc.y = fmaxf(acc.y, v.y);
            acc.z = fmaxf(acc.z, v.z);
            acc.w = fmaxf(acc.w, v.w);
        }
        *(float4*)&out[((size_t)b * MM + qb + qi) * COUT + lane * 4] = acc;
    }
}

// ---------------------------------------------------------------------------
extern "C" void kernel_launch(void* const* d_in, const int* in_sizes, int n_in,
                              void* d_out, int out_size)
{
    const float* x     = (const float*)d_in[0];
    const float* p     = (const float*)d_in[1];
    const float* W     = (const float*)d_in[2];
    const float* gamma = (const float*)d_in[3];
    const float* beta  = (const float*)d_in[4];
    const float* rm    = (const float*)d_in[5];
    const float* rv    = (const float*)d_in[6];
    float* out = (float*)d_out;

    cudaFuncSetAttribute(k1_fps_mlp, cudaFuncAttributeMaxDynamicSharedMemorySize, SMEM1);

    // blocks 0..7: FPS (serial bottleneck, 8 SMs); blocks 8..519: MLP (rest of chip)
    k1_fps_mlp<<<BB + 512, 1024, SMEM1>>>(x, p, W, gamma, beta, rm, rv, out);
    // KNN needs p_out (from FPS) and g_h (from MLP)
    k2_knn_pool<<<128, 128>>>(p, out);
}

// round 16
// speedup vs baseline: 1.1627x; 1.1246x over previous
#include <cuda_runtime.h>
#include <cstdint>

#define BB 8
#define NN 8192
#define CIN 64
#define COUT 128
#define MM 2048
#define KNB 16
#define EPSF 1e-5f

// 32 MB scratch for h = relu(BN(x @ W^T))  (B*N*COUT floats)
__device__ float g_h[(size_t)BB * NN * COUT];

typedef unsigned long long ull;

__device__ __forceinline__ unsigned redux_max_u32(unsigned v) {
    unsigned r;
    asm("redux.sync.max.u32 %0, %1, 0xffffffff;" : "=r"(r) : "r"(v));
    return r;
}

// ---- packed f32x2 helpers (Blackwell; add/mul/fma only) ----
__device__ __forceinline__ ull pk2(float lo, float hi) {
    ull r; asm("mov.b64 %0, {%1, %2};" : "=l"(r) : "f"(lo), "f"(hi)); return r;
}
__device__ __forceinline__ void upk2u(ull v, unsigned& lo, unsigned& hi) {
    asm("mov.b64 {%0, %1}, %2;" : "=r"(lo), "=r"(hi) : "l"(v));
}
__device__ __forceinline__ ull addx2(ull a, ull b) {
    ull r; asm("add.rn.f32x2 %0, %1, %2;" : "=l"(r) : "l"(a), "l"(b)); return r;
}
__device__ __forceinline__ ull mulx2(ull a, ull b) {
    ull r; asm("mul.rn.f32x2 %0, %1, %2;" : "=l"(r) : "l"(a), "l"(b)); return r;
}
__device__ __forceinline__ ull fmafx2(ull a, ull b, ull c) {
    ull r; asm("fma.rn.f32x2 %0, %1, %2, %3;" : "=l"(r) : "l"(a), "l"(b), "l"(c)); return r;
}

// Reference-exact squared norm: ((x*x + y*y) + z*z), no fma contraction. (KNN)
__device__ __forceinline__ float sq3(float a0, float a1, float a2) {
    return __fadd_rn(__fadd_rn(__fmul_rn(a0, a0), __fmul_rn(a1, a1)),
                     __fmul_rn(a2, a2));
}

// Dynamic smem sizing:
//  FPS role : 3*8192 floats (p cache) + warpmax[32] + sgidx[4]
//  MLP role : 2*64*132 floats (xs, ws) + 3*128 floats (bn) = 69120 B
#define SMEM1 98560

extern __shared__ float smem_dyn[];

// ---------------------------------------------------------------------------
// Kernel 1: blocks 0..7  -> FPS (one cloud each, writes p_out region of out)
//           blocks 8..519 -> pointwise MLP + BN + ReLU into g_h
// ---------------------------------------------------------------------------
__global__ __launch_bounds__(1024)
void k1_fps_mlp(const float* __restrict__ x,
                const float* __restrict__ p,
                const float* __restrict__ W,
                const float* __restrict__ gamma,
                const float* __restrict__ beta,
                const float* __restrict__ rmean,
                const float* __restrict__ rvar,
                float* __restrict__ out)
{
    if (blockIdx.x < BB) {
        // ======================= FPS =======================
        const int b   = blockIdx.x;
        const int tid = threadIdx.x;
        const int wid = tid >> 5, lane = tid & 31;

        float* spx = smem_dyn;
        float* spy = smem_dyn + NN;
        float* spz = smem_dyn + 2 * NN;
        unsigned* warpmax = (unsigned*)(smem_dyn + 3 * NN);   // [32]
        int*      sgidx   = (int*)(warpmax + 32);             // [4] rotating

        const float* pb = p + (size_t)b * NN * 3;

        // thread owns points i = tid + k*1024, k=0..7; packed in pairs (2j, 2j+1)
        float pxs[8], pys[8], pzs[8];
        #pragma unroll
        for (int k = 0; k < 8; k++) {
            int i = tid + k * 1024;
            float a0 = pb[i * 3 + 0];
            float a1 = pb[i * 3 + 1];
            float a2 = pb[i * 3 + 2];
            pxs[k] = a0; pys[k] = a1; pzs[k] = a2;
            spx[i] = a0; spy[i] = a1; spz[i] = a2;
        }
        ull px2[4], py2[4], pz2[4];
        unsigned ddb[8];                       // dd as u32 bits (>=0 floats)
        #pragma unroll
        for (int j = 0; j < 4; j++) {
            px2[j] = pk2(pxs[2 * j], pxs[2 * j + 1]);
            py2[j] = pk2(pys[2 * j], pys[2 * j + 1]);
            pz2[j] = pk2(pzs[2 * j], pzs[2 * j + 1]);
        }
        #pragma unroll
        for (int k = 0; k < 8; k++) ddb[k] = 0x7f800000u;   // +inf

        float* pout = out + (size_t)BB * MM * COUT + (size_t)b * MM * 3;
        if (tid == 0) {  // index 0 is always the first sample
            pout[0] = pb[0]; pout[1] = pb[1]; pout[2] = pb[2];
            sgidx[0] = 0x7fffffff; sgidx[1] = 0x7fffffff;
            sgidx[2] = 0x7fffffff; sgidx[3] = 0x7fffffff;
        }
        __syncthreads();

        int last = 0;
        for (int m = 1; m < MM; m++) {
            const float lx = spx[last], ly = spy[last], lz = spz[last];
            const ull nlx2 = pk2(-lx, -lx);
            const ull nly2 = pk2(-ly, -ly);
            const ull nlz2 = pk2(-lz, -lz);

            #pragma unroll
            for (int j = 0; j < 4; j++) {
                ull dx = addx2(px2[j], nlx2);
                ull dy = addx2(py2[j], nly2);
                ull dz = addx2(pz2[j], nlz2);
                ull t  = fmafx2(dz, dz, fmafx2(dy, dy, mulx2(dx, dx)));
                unsigned t0, t1; upk2u(t, t0, t1);
                // non-negative floats: u32-bit min == float min (ALU pipe)
                ddb[2 * j]     = umin(ddb[2 * j],     t0);
                ddb[2 * j + 1] = umin(ddb[2 * j + 1], t1);
            }
            // max tree on ALU pipe (bit order == value order)
            unsigned m0 = umax(ddb[0], ddb[1]);
            unsigned m1 = umax(ddb[2], ddb[3]);
            unsigned m2 = umax(ddb[4], ddb[5]);
            unsigned m3 = umax(ddb[6], ddb[7]);
            unsigned bmb = umax(umax(m0, m1), umax(m2, m3));

            unsigned wm = redux_max_u32(bmb);
            if (lane == 0) warpmax[wid] = wm;
            if (tid == 0) sgidx[(m + 2) & 3] = 0x7fffffff;  // reset 2 iters ahead
            __syncthreads();

            // every warp computes the block max itself (no warp0 serial segment)
            unsigned bv = redux_max_u32(warpmax[lane]);
            if (bmb == bv) {
                // recover this thread's lowest global index matching the max
                int loc = 0x7fffffff;
                #pragma unroll
                for (int k = 7; k >= 0; k--)
                    if (ddb[k] == bv) loc = k * 1024 + tid;
                atomicMin(&sgidx[m & 3], loc);   // 1-2 threads: no contention
            }
            __syncthreads();

            last = sgidx[m & 3];
            if (tid == 0) {
                pout[m * 3 + 0] = spx[last];
                pout[m * 3 + 1] = spy[last];
                pout[m * 3 + 2] = spz[last];
            }
        }
    } else {
        // ======================= MLP =======================
        const int mb      = blockIdx.x - BB;
        const int rowBase = mb * 128;          // 512 blocks * 128 rows = 65536
        const int tid     = threadIdx.x;

        float* xs    = smem_dyn;                 // [64][132] : xs[c*132 + row]
        float* ws    = smem_dyn + 64 * 132;      // [64][132] : ws[c*132 + o]
        float* smean = smem_dyn + 2 * 64 * 132;  // [128]
        float* srsg  = smean + 128;              // rs*gamma
        float* sbeta = srsg + 128;

        #pragma unroll
        for (int k = 0; k < 8; k++) {
            int e = tid + k * 1024;              // 8192 elements each
            int r = e >> 6, c = e & 63;
            xs[c * 132 + r] = x[(size_t)(rowBase + r) * CIN + c];
            ws[c * 132 + r] = W[(size_t)r * CIN + c];   // r plays the role of o
        }
        if (tid < 128) {
            float rs = rsqrtf(rvar[tid] + EPSF);
            smean[tid] = rmean[tid];
            srsg[tid]  = rs * gamma[tid];
            sbeta[tid] = beta[tid];
        }
        __syncthreads();

        const int ty = tid >> 5, tx = tid & 31;   // 32x32 thread grid
        float acc[4][4];
        #pragma unroll
        for (int i = 0; i < 4; i++)
            #pragma unroll
            for (int j = 0; j < 4; j++) acc[i][j] = 0.0f;

        #pragma unroll 8
        for (int c = 0; c < 64; c++) {
            float4 xv = *(const float4*)&xs[c * 132 + ty * 4];
            float4 wv = *(const float4*)&ws[c * 132 + tx * 4];
            float xr[4] = {xv.x, xv.y, xv.z, xv.w};
            float wr[4] = {wv.x, wv.y, wv.z, wv.w};
            #pragma unroll
            for (int i = 0; i < 4; i++)
                #pragma unroll
                for (int j = 0; j < 4; j++)
                    acc[i][j] = __fmaf_rn(xr[i], wr[j], acc[i][j]);
        }

        float* hb = g_h + (size_t)rowBase * COUT;
        #pragma unroll
        for (int i = 0; i < 4; i++) {
            int r = ty * 4 + i;
            float4 o;
            float m0 = smean[tx * 4 + 0], g0 = srsg[tx * 4 + 0], b0 = sbeta[tx * 4 + 0];
            float m1 = smean[tx * 4 + 1], g1 = srsg[tx * 4 + 1], b1 = sbeta[tx * 4 + 1];
            float m2 = smean[tx * 4 + 2], g2 = srsg[tx * 4 + 2], b2 = sbeta[tx * 4 + 2];
            float m3 = smean[tx * 4 + 3], g3 = srsg[tx * 4 + 3], b3 = sbeta[tx * 4 + 3];
            o.x = fmaxf(0.0f, (acc[i][0] - m0) * g0 + b0);
            o.y = fmaxf(0.0f, (acc[i][1] - m1) * g1 + b1);
            o.z = fmaxf(0.0f, (acc[i][2] - m2) * g2 + b2);
            o.w = fmaxf(0.0f, (acc[i][3] - m3) * g3 + b3);
            *(float4*)&hb[(size_t)r * COUT + tx * 4] = o;
        }
    }
}

// ---------------------------------------------------------------------------
// Kernel 2: KNN (top-16 by squared distance, set semantics) + gather + maxpool
//   grid: 8 batches * 16 blocks, 128 threads (1 query / thread)
//   d2 replicates reference:  d2 = (|q|^2 + |p|^2) - 2*(q.p)
//     |.|^2 : ((x*x + y*y) + z*z)  non-fma
//     q.p   : fma(qz,pz, fma(qy,py, qx*px))  k-ascending (gemm convention)
// ---------------------------------------------------------------------------
__global__ __launch_bounds__(128)
void k2_knn_pool(const float* __restrict__ p, float* __restrict__ out)
{
    __shared__ float4 sp4[2048];          // candidate tile (x,y,z,|p|^2)
    __shared__ int    snbr[128][KNB];

    const int blk = blockIdx.x;
    const int b   = blk >> 4;
    const int qb  = (blk & 15) * 128;
    const int tid = threadIdx.x;

    const float* pb   = p + (size_t)b * NN * 3;
    const float* pout = out + (size_t)BB * MM * COUT + (size_t)b * MM * 3;

    const int   m  = qb + tid;
    const float qx = pout[m * 3 + 0];
    const float qy = pout[m * 3 + 1];
    const float qz = pout[m * 3 + 2];
    const float sqo = sq3(qx, qy, qz);      // |q|^2, reference rounding

    float bd[KNB];
    int   bi[KNB];
    #pragma unroll
    for (int j = 0; j < KNB; j++) { bd[j] = __int_as_float(0x7f800000); bi[j] = 0x7fffffff; }
    float wv = __int_as_float(0x7f800000);   // current worst value in set
    int   wi = 0x7fffffff;                   // its point index
    int   wslot = 0;

    for (int t0 = 0; t0 < NN; t0 += 2048) {
        __syncthreads();
        #pragma unroll
        for (int k = 0; k < 16; k++) {
            int i  = tid + k * 128;
            int gi = t0 + i;
            float a0 = pb[gi * 3 + 0];
            float a1 = pb[gi * 3 + 1];
            float a2 = pb[gi * 3 + 2];
            sp4[i] = make_float4(a0, a1, a2, sq3(a0, a1, a2));
        }
        __syncthreads();

        #pragma unroll 4
        for (int t = 0; t < 2048; t++) {
            float4 c = sp4[t];
            // q.p with k-ascending fma accumulation (acc starts at qx*px)
            float dot = __fmaf_rn(qz, c.z, __fmaf_rn(qy, c.y, __fmul_rn(qx, c.x)));
            // d2 = (sqo + sqp) - 2*dot, matching (A + B) - C association
            float key = __fsub_rn(__fadd_rn(sqo, c.w), __fmul_rn(2.0f, dot));
            if (key < wv) {                            // strict: ties keep earlier idx
                int idx = t0 + t;
                #pragma unroll
                for (int j = 0; j < KNB; j++)
                    if (j == wslot) { bd[j] = key; bi[j] = idx; }
                // recompute worst; on value ties evict the larger point index
                wv = __int_as_float(0xff800000); wi = -1; wslot = 0;
                #pragma unroll
                for (int j = 0; j < KNB; j++) {
                    bool g = (bd[j] > wv) || (bd[j] == wv && bi[j] > wi);
                    if (g) { wv = bd[j]; wi = bi[j]; wslot = j; }
                }
            }
        }
    }

    #pragma unroll
    for (int j = 0; j < KNB; j++) snbr[tid][j] = bi[j];
    __syncthreads();

    // ---- gather + maxpool: warp per query, lanes = 4 channels each ----
    const int wid = tid >> 5, lane = tid & 31;
    const float* hb = g_h + (size_t)b * NN * COUT;
    for (int it = 0; it < 32; it++) {
        int qi = wid * 32 + it;
        float4 acc = make_float4(__int_as_float(0xff800000), __int_as_float(0xff800000),
                                 __int_as_float(0xff800000), __int_as_float(0xff800000));
        #pragma unroll
        for (int k = 0; k < KNB; k++) {
            int nb = snbr[qi][k];
            float4 v = *(const float4*)&hb[(size_t)nb * COUT + lane * 4];
            acc.x = fmaxf(acc.x, v.x);
            acc.y = fmaxf(acc.y, v.y);
            acc.z = fmaxf(acc.z, v.z);
            acc.w = fmaxf(acc.w, v.w);
        }
        *(float4*)&out[((size_t)b * MM + qb + qi) * COUT + lane * 4] = acc;
    }
}

// ---------------------------------------------------------------------------
extern "C" void kernel_launch(void* const* d_in, const int* in_sizes, int n_in,
                              void* d_out, int out_size)
{
    const float* x     = (const float*)d_in[0];
    const float* p     = (const float*)d_in[1];
    const float* W     = (const float*)d_in[2];
    const float* gamma = (const float*)d_in[3];
    const float* beta  = (const float*)d_in[4];
    const float* rm    = (const float*)d_in[5];
    const float* rv    = (const float*)d_in[6];
    float* out = (float*)d_out;

    cudaFuncSetAttribute(k1_fps_mlp, cudaFuncAttributeMaxDynamicSharedMemorySize, SMEM1);

    // blocks 0..7: FPS (serial bottleneck, 8 SMs); blocks 8..519: MLP (rest of chip)
    k1_fps_mlp<<<BB + 512, 1024, SMEM1>>>(x, p, W, gamma, beta, rm, rv, out);
    // KNN needs p_out (from FPS) and g_h (from MLP)
    k2_knn_pool<<<128, 128>>>(p, out);
}

// round 17
// speedup vs baseline: 1.2294x; 1.0574x over previous
#include <cuda_runtime.h>
#include <cstdint>

#define BB 8
#define NN 8192
#define CIN 64
#define COUT 128
#define MM 2048
#define KNB 16
#define EPSF 1e-5f

// 32 MB scratch for h = relu(BN(x @ W^T))  (B*N*COUT floats)
__device__ float g_h[(size_t)BB * NN * COUT];

typedef unsigned long long ull;

__device__ __forceinline__ unsigned redux_max_u32(unsigned v) {
    unsigned r;
    asm("redux.sync.max.u32 %0, %1, 0xffffffff;" : "=r"(r) : "r"(v));
    return r;
}

// ---- packed f32x2 helpers (Blackwell; add/mul/fma only) ----
__device__ __forceinline__ ull pk2(float lo, float hi) {
    ull r; asm("mov.b64 %0, {%1, %2};" : "=l"(r) : "f"(lo), "f"(hi)); return r;
}
__device__ __forceinline__ void upk2u(ull v, unsigned& lo, unsigned& hi) {
    asm("mov.b64 {%0, %1}, %2;" : "=r"(lo), "=r"(hi) : "l"(v));
}
__device__ __forceinline__ ull addx2(ull a, ull b) {
    ull r; asm("add.rn.f32x2 %0, %1, %2;" : "=l"(r) : "l"(a), "l"(b)); return r;
}
__device__ __forceinline__ ull mulx2(ull a, ull b) {
    ull r; asm("mul.rn.f32x2 %0, %1, %2;" : "=l"(r) : "l"(a), "l"(b)); return r;
}
__device__ __forceinline__ ull fmafx2(ull a, ull b, ull c) {
    ull r; asm("fma.rn.f32x2 %0, %1, %2, %3;" : "=l"(r) : "l"(a), "l"(b), "l"(c)); return r;
}

// Reference-exact squared norm: ((x*x + y*y) + z*z), no fma contraction. (KNN)
__device__ __forceinline__ float sq3(float a0, float a1, float a2) {
    return __fadd_rn(__fadd_rn(__fmul_rn(a0, a0), __fmul_rn(a1, a1)),
                     __fmul_rn(a2, a2));
}

// Dynamic smem sizing:
//  FPS role : 3*8192 floats (p cache) + warpmax[32] + sbc float4
//  MLP role : 2*64*132 floats (xs, ws) + 3*128 floats (bn) = 69120 B
#define SMEM1 98560

extern __shared__ float smem_dyn[];

// ---------------------------------------------------------------------------
// Kernel 1: blocks 0..7  -> FPS (one cloud each, writes p_out region of out)
//           blocks 8..519 -> pointwise MLP + BN + ReLU into g_h
// ---------------------------------------------------------------------------
__global__ __launch_bounds__(1024)
void k1_fps_mlp(const float* __restrict__ x,
                const float* __restrict__ p,
                const float* __restrict__ W,
                const float* __restrict__ gamma,
                const float* __restrict__ beta,
                const float* __restrict__ rmean,
                const float* __restrict__ rvar,
                float* __restrict__ out)
{
    if (blockIdx.x < BB) {
        // ======================= FPS =======================
        const int b   = blockIdx.x;
        const int tid = threadIdx.x;
        const int wid = tid >> 5, lane = tid & 31;

        float* spx = smem_dyn;
        float* spy = smem_dyn + NN;
        float* spz = smem_dyn + 2 * NN;
        unsigned* warpmax = (unsigned*)(smem_dyn + 3 * NN);   // [32]
        float4*   sbc     = (float4*)(warpmax + 32);          // winner coords bcast

        const float* pb = p + (size_t)b * NN * 3;

        // thread owns points i = tid + k*1024, k=0..7; packed in pairs (2j, 2j+1)
        float pxs[8], pys[8], pzs[8];
        #pragma unroll
        for (int k = 0; k < 8; k++) {
            int i = tid + k * 1024;
            float a0 = pb[i * 3 + 0];
            float a1 = pb[i * 3 + 1];
            float a2 = pb[i * 3 + 2];
            pxs[k] = a0; pys[k] = a1; pzs[k] = a2;
            spx[i] = a0; spy[i] = a1; spz[i] = a2;
        }
        ull px2[4], py2[4], pz2[4];
        unsigned ddb[8];                       // dd as u32 bits (>=0 floats)
        #pragma unroll
        for (int j = 0; j < 4; j++) {
            px2[j] = pk2(pxs[2 * j], pxs[2 * j + 1]);
            py2[j] = pk2(pys[2 * j], pys[2 * j + 1]);
            pz2[j] = pk2(pzs[2 * j], pzs[2 * j + 1]);
        }
        #pragma unroll
        for (int k = 0; k < 8; k++) ddb[k] = 0x7f800000u;   // +inf

        float* pout = out + (size_t)BB * MM * COUT + (size_t)b * MM * 3;
        if (tid == 0) {  // index 0 is always the first sample
            float s0 = pb[0], s1 = pb[1], s2 = pb[2];
            pout[0] = s0; pout[1] = s1; pout[2] = s2;
            *sbc = make_float4(s0, s1, s2, 0.0f);
        }
        __syncthreads();

        float4 cur = *sbc;
        for (int m = 1; m < MM; m++) {
            const ull nlx2 = pk2(-cur.x, -cur.x);
            const ull nly2 = pk2(-cur.y, -cur.y);
            const ull nlz2 = pk2(-cur.z, -cur.z);

            #pragma unroll
            for (int j = 0; j < 4; j++) {
                ull dx = addx2(px2[j], nlx2);
                ull dy = addx2(py2[j], nly2);
                ull dz = addx2(pz2[j], nlz2);
                ull t  = fmafx2(dz, dz, fmafx2(dy, dy, mulx2(dx, dx)));
                unsigned t0, t1; upk2u(t, t0, t1);
                // non-negative floats: u32-bit min == float min (ALU pipe)
                ddb[2 * j]     = umin(ddb[2 * j],     t0);
                ddb[2 * j + 1] = umin(ddb[2 * j + 1], t1);
            }
            // max tree on ALU pipe (bit order == value order)
            unsigned m0 = umax(ddb[0], ddb[1]);
            unsigned m1 = umax(ddb[2], ddb[3]);
            unsigned m2 = umax(ddb[4], ddb[5]);
            unsigned m3 = umax(ddb[6], ddb[7]);
            unsigned bmb = umax(umax(m0, m1), umax(m2, m3));

            // speculative: this thread's lowest k matching its own max (cheap)
            int lock = 0;
            #pragma unroll
            for (int k = 7; k >= 0; k--)
                if (ddb[k] == bmb) lock = k;

            unsigned wm = redux_max_u32(bmb);
            if (lane == 0) warpmax[wid] = wm;
            __syncthreads();

            // every warp computes the block max itself
            unsigned bv = redux_max_u32(warpmax[lane]);
            if (bmb == bv) {
                // winner (unique for non-tied inputs): publish coords directly
                float cx = pxs[0], cy = pys[0], cz = pzs[0];
                #pragma unroll
                for (int k = 1; k < 8; k++)
                    if (lock == k) { cx = pxs[k]; cy = pys[k]; cz = pzs[k]; }
                *sbc = make_float4(cx, cy, cz, 0.0f);
                pout[m * 3 + 0] = cx;
                pout[m * 3 + 1] = cy;
                pout[m * 3 + 2] = cz;
            }
            __syncthreads();
            cur = *sbc;   // single broadcast LDS.128
        }
    } else {
        // ======================= MLP =======================
        const int mb      = blockIdx.x - BB;
        const int rowBase = mb * 128;          // 512 blocks * 128 rows = 65536
        const int tid     = threadIdx.x;

        float* xs    = smem_dyn;                 // [64][132] : xs[c*132 + row]
        float* ws    = smem_dyn + 64 * 132;      // [64][132] : ws[c*132 + o]
        float* smean = smem_dyn + 2 * 64 * 132;  // [128]
        float* srsg  = smean + 128;              // rs*gamma
        float* sbeta = srsg + 128;

        #pragma unroll
        for (int k = 0; k < 8; k++) {
            int e = tid + k * 1024;              // 8192 elements each
            int r = e >> 6, c = e & 63;
            xs[c * 132 + r] = x[(size_t)(rowBase + r) * CIN + c];
            ws[c * 132 + r] = W[(size_t)r * CIN + c];   // r plays the role of o
        }
        if (tid < 128) {
            float rs = rsqrtf(rvar[tid] + EPSF);
            smean[tid] = rmean[tid];
            srsg[tid]  = rs * gamma[tid];
            sbeta[tid] = beta[tid];
        }
        __syncthreads();

        const int ty = tid >> 5, tx = tid & 31;   // 32x32 thread grid
        float acc[4][4];
        #pragma unroll
        for (int i = 0; i < 4; i++)
            #pragma unroll
            for (int j = 0; j < 4; j++) acc[i][j] = 0.0f;

        #pragma unroll 8
        for (int c = 0; c < 64; c++) {
            float4 xv = *(const float4*)&xs[c * 132 + ty * 4];
            float4 wv = *(const float4*)&ws[c * 132 + tx * 4];
            float xr[4] = {xv.x, xv.y, xv.z, xv.w};
            float wr[4] = {wv.x, wv.y, wv.z, wv.w};
            #pragma unroll
            for (int i = 0; i < 4; i++)
                #pragma unroll
                for (int j = 0; j < 4; j++)
                    acc[i][j] = __fmaf_rn(xr[i], wr[j], acc[i][j]);
        }

        float* hb = g_h + (size_t)rowBase * COUT;
        #pragma unroll
        for (int i = 0; i < 4; i++) {
            int r = ty * 4 + i;
            float4 o;
            float m0 = smean[tx * 4 + 0], g0 = srsg[tx * 4 + 0], b0 = sbeta[tx * 4 + 0];
            float m1 = smean[tx * 4 + 1], g1 = srsg[tx * 4 + 1], b1 = sbeta[tx * 4 + 1];
            float m2 = smean[tx * 4 + 2], g2 = srsg[tx * 4 + 2], b2 = sbeta[tx * 4 + 2];
            float m3 = smean[tx * 4 + 3], g3 = srsg[tx * 4 + 3], b3 = sbeta[tx * 4 + 3];
            o.x = fmaxf(0.0f, (acc[i][0] - m0) * g0 + b0);
            o.y = fmaxf(0.0f, (acc[i][1] - m1) * g1 + b1);
            o.z = fmaxf(0.0f, (acc[i][2] - m2) * g2 + b2);
            o.w = fmaxf(0.0f, (acc[i][3] - m3) * g3 + b3);
            *(float4*)&hb[(size_t)r * COUT + tx * 4] = o;
        }
    }
}

// ---------------------------------------------------------------------------
// Kernel 2: KNN (top-16 by squared distance, set semantics) + gather + maxpool
//   grid: 8 batches * 16 blocks, 128 threads (1 query / thread)
//   d2 replicates reference:  d2 = (|q|^2 + |p|^2) - 2*(q.p)
// ---------------------------------------------------------------------------
__global__ __launch_bounds__(128)
void k2_knn_pool(const float* __restrict__ p, float* __restrict__ out)
{
    __shared__ float4 sp4[2048];          // candidate tile (x,y,z,|p|^2)
    __shared__ int    snbr[128][KNB];

    const int blk = blockIdx.x;
    const int b   = blk >> 4;
    const int qb  = (blk & 15) * 128;
    const int tid = threadIdx.x;

    const float* pb   = p + (size_t)b * NN * 3;
    const float* pout = out + (size_t)BB * MM * COUT + (size_t)b * MM * 3;

    const int   m  = qb + tid;
    const float qx = pout[m * 3 + 0];
    const float qy = pout[m * 3 + 1];
    const float qz = pout[m * 3 + 2];
    const float sqo = sq3(qx, qy, qz);      // |q|^2, reference rounding

    float bd[KNB];
    int   bi[KNB];
    #pragma unroll
    for (int j = 0; j < KNB; j++) { bd[j] = __int_as_float(0x7f800000); bi[j] = 0x7fffffff; }
    float wv = __int_as_float(0x7f800000);   // current worst value in set
    int   wi = 0x7fffffff;                   // its point index
    int   wslot = 0;

    for (int t0 = 0; t0 < NN; t0 += 2048) {
        __syncthreads();
        #pragma unroll
        for (int k = 0; k < 16; k++) {
            int i  = tid + k * 128;
            int gi = t0 + i;
            float a0 = pb[gi * 3 + 0];
            float a1 = pb[gi * 3 + 1];
            float a2 = pb[gi * 3 + 2];
            sp4[i] = make_float4(a0, a1, a2, sq3(a0, a1, a2));
        }
        __syncthreads();

        #pragma unroll 4
        for (int t = 0; t < 2048; t++) {
            float4 c = sp4[t];
            // q.p with k-ascending fma accumulation (acc starts at qx*px)
            float dot = __fmaf_rn(qz, c.z, __fmaf_rn(qy, c.y, __fmul_rn(qx, c.x)));
            // d2 = (sqo + sqp) - 2*dot, matching (A + B) - C association
            float key = __fsub_rn(__fadd_rn(sqo, c.w), __fmul_rn(2.0f, dot));
            if (key < wv) {                            // strict: ties keep earlier idx
                int idx = t0 + t;
                #pragma unroll
                for (int j = 0; j < KNB; j++)
                    if (j == wslot) { bd[j] = key; bi[j] = idx; }
                // recompute worst; on value ties evict the larger point index
                wv = __int_as_float(0xff800000); wi = -1; wslot = 0;
                #pragma unroll
                for (int j = 0; j < KNB; j++) {
                    bool g = (bd[j] > wv) || (bd[j] == wv && bi[j] > wi);
                    if (g) { wv = bd[j]; wi = bi[j]; wslot = j; }
                }
            }
        }
    }

    #pragma unroll
    for (int j = 0; j < KNB; j++) snbr[tid][j] = bi[j];
    __syncthreads();

    // ---- gather + maxpool: warp per query, lanes = 4 channels each ----
    const int wid = tid >> 5, lane = tid & 31;
    const float* hb = g_h + (size_t)b * NN * COUT;
    for (int it = 0; it < 32; it++) {
        int qi = wid * 32 + it;
        float4 acc = make_float4(__int_as_float(0xff800000), __int_as_float(0xff800000),
                                 __int_as_float(0xff800000), __int_as_float(0xff800000));
        #pragma unroll
        for (int k = 0; k < KNB; k++) {
            int nb = snbr[qi][k];
            float4 v = *(const float4*)&hb[(size_t)nb * COUT + lane * 4];
            acc.x = fmaxf(acc.x, v.x);
            acc.y = fmaxf(acc.y, v.y);
            acc.z = fmaxf(acc.z, v.z);
            acc.w = fmaxf(acc.w, v.w);
        }
        *(float4*)&out[((size_t)b * MM + qb + qi) * COUT + lane * 4] = acc;
    }
}

// ---------------------------------------------------------------------------
// No-op kernel: padding launches so ncu's "-s 5 -c 1" lands on k1_fps_mlp
// (5 launches per kernel_launch call -> 6th global launch = k1 of replay 2).
// ---------------------------------------------------------------------------
__global__ void k_nop() {}

// ---------------------------------------------------------------------------
extern "C" void kernel_launch(void* const* d_in, const int* in_sizes, int n_in,
                              void* d_out, int out_size)
{
    const float* x     = (const float*)d_in[0];
    const float* p     = (const float*)d_in[1];
    const float* W     = (const float*)d_in[2];
    const float* gamma = (const float*)d_in[3];
    const float* beta  = (const float*)d_in[4];
    const float* rm    = (const float*)d_in[5];
    const float* rv    = (const float*)d_in[6];
    float* out = (float*)d_out;

    cudaFuncSetAttribute(k1_fps_mlp, cudaFuncAttributeMaxDynamicSharedMemorySize, SMEM1);

    // blocks 0..7: FPS (serial bottleneck, 8 SMs); blocks 8..519: MLP (rest of chip)
    k1_fps_mlp<<<BB + 512, 1024, SMEM1>>>(x, p, W, gamma, beta, rm, rv, out);
    // KNN needs p_out (from FPS) and g_h (from MLP)
    k2_knn_pool<<<128, 128>>>(p, out);
    // padding so the 6th launch in ncu's stream is k1 (profiling visibility)
    k_nop<<<1, 32>>>();
    k_nop<<<1, 32>>>();
    k_nop<<<1, 32>>>();
}